// round 2
// baseline (speedup 1.0000x reference)
#include <cuda_runtime.h>
#include <cstdint>

#define BB 64
#define TT 256
#define UU 512
#define GG 2048
#define BT (BB*TT)

#define NBLK 128
#define HSTR 68                                   // padded h_s stride
#define SCAN_SMEM ((512*32 + 512*HSTR) * 4)       // w_s 64KB + h_s 136KB = 204800B

// ---------------- static scratch ----------------
__device__ __align__(128) float g_x0 [BT * 512];
__device__ __align__(128) float g_y0 [BT * 1024];
__device__ __align__(128) float g_xzf[BT * GG];
__device__ __align__(128) float g_xzb[BT * GG];
__device__ __align__(128) float g_h  [2 * 2 * UU * BB];   // [buf][dir][u][r], transposed
__device__ unsigned g_bar_count = 0;
__device__ unsigned g_bar_gen   = 0;

// ---------------- packed fp32 helpers ----------------
__device__ __forceinline__ void fma2(unsigned long long& d, unsigned long long a,
                                     unsigned long long b) {
    asm("fma.rn.f32x2 %0, %1, %2, %0;" : "+l"(d) : "l"(a), "l"(b));
}
__device__ __forceinline__ unsigned long long pk2(float a, float b) {
    unsigned long long r; asm("mov.b64 %0, {%1,%2};" : "=l"(r) : "f"(a), "f"(b)); return r;
}
__device__ __forceinline__ float2 up2(unsigned long long u) {
    float2 f; asm("mov.b64 {%0,%1}, %2;" : "=f"(f.x), "=f"(f.y) : "l"(u)); return f;
}
__device__ __forceinline__ float sigf(float x) { return 1.0f / (1.0f + expf(-x)); }

__device__ __forceinline__ void grid_barrier() {
    __syncthreads();
    if (threadIdx.x == 0) {
        __threadfence();
        unsigned gen = *(volatile unsigned*)&g_bar_gen;
        if (atomicAdd(&g_bar_count, 1u) == NBLK - 1) {
            g_bar_count = 0;
            __threadfence();
            *(volatile unsigned*)&g_bar_gen = gen + 1;
        } else {
            while (*(volatile unsigned*)&g_bar_gen == gen) { }
        }
    }
    __syncthreads();
}

// ---------------- embedding gather ----------------
__global__ void embed_kernel(const int* __restrict__ tokens,
                             const float* __restrict__ emb,
                             float* __restrict__ x0) {
    int i = blockIdx.x * 256 + threadIdx.x;     // over BT*512/4
    if (i >= BT * 128) return;
    int row = i >> 7;
    int c4  = (i & 127) << 2;
    int tok = tokens[row];
    *(float4*)&x0[row * 512 + c4] = *(const float4*)&emb[tok * 512 + c4];
}

// ---------------- SGEMM: C = A(MxK) @ W(KxN) + bias, f32x2 packed ----------------
__global__ void __launch_bounds__(256)
sgemm_bias(const float* __restrict__ A, const float* __restrict__ W,
           const float* __restrict__ bias, float* __restrict__ C,
           int M, int N, int K) {
    __shared__ float As_t[8][128];   // [k][row]
    __shared__ float Bs2 [8][256];   // [k][2*col] duplicated

    int tid = threadIdx.x;
    int bm = blockIdx.y * 128;
    int bn = blockIdx.x * 128;
    int tx = tid & 15, ty = tid >> 4;

    int a_row = tid >> 1;
    int a_col = (tid & 1) * 4;
    int b_row = tid >> 5;
    int b_col = (tid & 31) * 4;

    unsigned long long acc[4][8];
    #pragma unroll
    for (int i = 0; i < 4; i++)
        #pragma unroll
        for (int j = 0; j < 8; j++) acc[i][j] = 0ull;

    const float* Ap = A + (bm + a_row) * K + a_col;
    const float* Wp = W + b_row * N + bn + b_col;

    for (int k0 = 0; k0 < K; k0 += 8) {
        float4 av = *(const float4*)(Ap + k0);
        float4 bv = *(const float4*)(Wp + k0 * N);
        __syncthreads();
        As_t[a_col + 0][a_row] = av.x;
        As_t[a_col + 1][a_row] = av.y;
        As_t[a_col + 2][a_row] = av.z;
        As_t[a_col + 3][a_row] = av.w;
        *(float2*)&Bs2[b_row][2 * (b_col + 0)] = make_float2(bv.x, bv.x);
        *(float2*)&Bs2[b_row][2 * (b_col + 1)] = make_float2(bv.y, bv.y);
        *(float2*)&Bs2[b_row][2 * (b_col + 2)] = make_float2(bv.z, bv.z);
        *(float2*)&Bs2[b_row][2 * (b_col + 3)] = make_float2(bv.w, bv.w);
        __syncthreads();

        #pragma unroll
        for (int k = 0; k < 8; k++) {
            ulonglong2 A0 = *(const ulonglong2*)&As_t[k][ty * 4];
            ulonglong2 A1 = *(const ulonglong2*)&As_t[k][64 + ty * 4];
            ulonglong2 B0 = *(const ulonglong2*)&Bs2[k][8 * tx];
            ulonglong2 B1 = *(const ulonglong2*)&Bs2[k][8 * tx + 4];
            ulonglong2 B2 = *(const ulonglong2*)&Bs2[k][128 + 8 * tx];
            ulonglong2 B3 = *(const ulonglong2*)&Bs2[k][128 + 8 * tx + 4];
            unsigned long long ap[4] = {A0.x, A0.y, A1.x, A1.y};
            unsigned long long bp[8] = {B0.x, B0.y, B1.x, B1.y, B2.x, B2.y, B3.x, B3.y};
            #pragma unroll
            for (int rp = 0; rp < 4; rp++)
                #pragma unroll
                for (int cj = 0; cj < 8; cj++)
                    fma2(acc[rp][cj], ap[rp], bp[cj]);
        }
    }

    float4 bs0 = *(const float4*)&bias[bn + tx * 4];
    float4 bs1 = *(const float4*)&bias[bn + 64 + tx * 4];
    float b0a[4] = {bs0.x, bs0.y, bs0.z, bs0.w};
    float b1a[4] = {bs1.x, bs1.y, bs1.z, bs1.w};

    #pragma unroll
    for (int rp = 0; rp < 4; rp++) {
        int r_lo = (rp < 2) ? (ty * 4 + rp * 2) : (64 + ty * 4 + (rp - 2) * 2);
        float2 v[8];
        #pragma unroll
        for (int cj = 0; cj < 8; cj++) v[cj] = up2(acc[rp][cj]);
        float4 o;
        float* Cr0 = C + (bm + r_lo) * N;
        float* Cr1 = C + (bm + r_lo + 1) * N;
        o = make_float4(v[0].x + b0a[0], v[1].x + b0a[1], v[2].x + b0a[2], v[3].x + b0a[3]);
        *(float4*)&Cr0[bn + tx * 4] = o;
        o = make_float4(v[0].y + b0a[0], v[1].y + b0a[1], v[2].y + b0a[2], v[3].y + b0a[3]);
        *(float4*)&Cr1[bn + tx * 4] = o;
        o = make_float4(v[4].x + b1a[0], v[5].x + b1a[1], v[6].x + b1a[2], v[7].x + b1a[3]);
        *(float4*)&Cr0[bn + 64 + tx * 4] = o;
        o = make_float4(v[4].y + b1a[0], v[5].y + b1a[1], v[6].y + b1a[2], v[7].y + b1a[3]);
        *(float4*)&Cr1[bn + 64 + tx * 4] = o;
    }
}

// ---------------- persistent bidirectional LSTM scan ----------------
// 128 blocks: blockIdx>>6 = dir, (blockIdx&63)*8 = first unit. One layer per launch.
__global__ void __launch_bounds__(256, 1)
lstm_scan(const float* __restrict__ xzf, const float* __restrict__ xzb,
          const float* __restrict__ Whf, const float* __restrict__ Whb,
          float* __restrict__ out, float* __restrict__ est_h, float* __restrict__ est_c) {
    extern __shared__ float sm[];
    float* w_s = sm;                 // [512][32]  col = ul*4 + gate
    float* h_s = sm + 512 * 32;      // [512][HSTR] transposed h

    int tid = threadIdx.x;
    int dir = blockIdx.x >> 6;
    int u0  = (blockIdx.x & 63) * 8;
    const float* xz = dir ? xzb : xzf;
    const float* Wh = dir ? Whb : Whf;

    for (int i = tid; i < 512 * 32; i += 256) {
        int k = i >> 5, c = i & 31, ul2 = c >> 2, g = c & 3;
        w_s[i] = Wh[k * GG + g * UU + u0 + ul2];
    }
    __syncthreads();

    int ul = tid & 7;
    int rp = tid >> 3;               // 0..31
    int r0 = 2 * rp, r1 = r0 + 1;
    int u  = u0 + ul;

    float c0 = 0.f, c1 = 0.f;

    for (int t = 0; t < TT; t++) {
        int ttv = dir ? (TT - 1 - t) : t;

        float z0[4], z1[4];
        #pragma unroll
        for (int g = 0; g < 4; g++) {
            z0[g] = xz[(r0 * TT + ttv) * GG + g * UU + u];
            z1[g] = xz[(r1 * TT + ttv) * GG + g * UU + u];
        }

        unsigned long long a00 = 0, a01 = 0, a10 = 0, a11 = 0;  // [row][(i,f)|(g,o)]

        if (t > 0) {
            const float* hg = g_h + ((t & 1) * 2 + dir) * (UU * BB);
            #pragma unroll 4
            for (int i = tid * 4; i < UU * BB; i += 256 * 4) {
                float4 v = __ldcg((const float4*)(hg + i));
                int uu2 = i >> 6, rr = i & 63;
                *(float4*)&h_s[uu2 * HSTR + rr] = v;
            }
            __syncthreads();

            #pragma unroll 8
            for (int k = 0; k < 512; k++) {
                float2 hv = *(const float2*)&h_s[k * HSTR + 2 * rp];
                ulonglong2 wv = *(const ulonglong2*)&w_s[k * 32 + ul * 4];
                unsigned long long hd0 = pk2(hv.x, hv.x);
                unsigned long long hd1 = pk2(hv.y, hv.y);
                fma2(a00, hd0, wv.x); fma2(a01, hd0, wv.y);
                fma2(a10, hd1, wv.x); fma2(a11, hd1, wv.y);
            }
        }

        float2 if0 = up2(a00), go0 = up2(a01);
        float2 if1 = up2(a10), go1 = up2(a11);

        float gi0 = sigf(z0[0] + if0.x), gf0 = sigf(z0[1] + if0.y);
        float gg0 = tanhf(z0[2] + go0.x), go0v = sigf(z0[3] + go0.y);
        c0 = gf0 * c0 + gi0 * gg0;
        float h0v = go0v * tanhf(c0);

        float gi1 = sigf(z1[0] + if1.x), gf1 = sigf(z1[1] + if1.y);
        float gg1 = tanhf(z1[2] + go1.x), go1v = sigf(z1[3] + go1.y);
        c1 = gf1 * c1 + gi1 * gg1;
        float h1v = go1v * tanhf(c1);

        float* hn = g_h + (((t + 1) & 1) * 2 + dir) * (UU * BB);
        hn[u * BB + r0] = h0v;
        hn[u * BB + r1] = h1v;

        out[(r0 * TT + ttv) * 1024 + dir * UU + u] = h0v;
        out[(r1 * TT + ttv) * 1024 + dir * UU + u] = h1v;

        if (est_h != nullptr && t == TT - 1) {
            est_h[r0 * 1024 + dir * UU + u] = h0v;
            est_h[r1 * 1024 + dir * UU + u] = h1v;
            est_c[r0 * 1024 + dir * UU + u] = c0;
            est_c[r1 * 1024 + dir * UU + u] = c1;
        }
        grid_barrier();
    }
}

// ---------------- launch ----------------
extern "C" void kernel_launch(void* const* d_in, const int* in_sizes, int n_in,
                              void* d_out, int out_size) {
    const int*   tokens = (const int*)  d_in[0];
    const float* emb    = (const float*)d_in[1];
    const float* Wx_f0 = (const float*)d_in[2];
    const float* Wh_f0 = (const float*)d_in[3];
    const float* b_f0  = (const float*)d_in[4];
    const float* Wx_b0 = (const float*)d_in[5];
    const float* Wh_b0 = (const float*)d_in[6];
    const float* b_b0  = (const float*)d_in[7];
    const float* Wx_f1 = (const float*)d_in[8];
    const float* Wh_f1 = (const float*)d_in[9];
    const float* b_f1  = (const float*)d_in[10];
    const float* Wx_b1 = (const float*)d_in[11];
    const float* Wh_b1 = (const float*)d_in[12];
    const float* b_b1  = (const float*)d_in[13];
    float* out = (float*)d_out;

    float *x0p, *y0p, *xzfp, *xzbp;
    cudaGetSymbolAddress((void**)&x0p,  g_x0);
    cudaGetSymbolAddress((void**)&y0p,  g_y0);
    cudaGetSymbolAddress((void**)&xzfp, g_xzf);
    cudaGetSymbolAddress((void**)&xzbp, g_xzb);

    cudaFuncSetAttribute(lstm_scan, cudaFuncAttributeMaxDynamicSharedMemorySize, SCAN_SMEM);

    embed_kernel<<<(BT * 128 + 255) / 256, 256>>>(tokens, emb, x0p);

    dim3 g0(GG / 128, BT / 128);
    sgemm_bias<<<g0, 256>>>(x0p, Wx_f0, b_f0, xzfp, BT, GG, 512);
    sgemm_bias<<<g0, 256>>>(x0p, Wx_b0, b_b0, xzbp, BT, GG, 512);

    lstm_scan<<<NBLK, 256, SCAN_SMEM>>>(xzfp, xzbp, Wh_f0, Wh_b0, y0p,
                                        (float*)nullptr, (float*)nullptr);

    sgemm_bias<<<g0, 256>>>(y0p, Wx_f1, b_f1, xzfp, BT, GG, 1024);
    sgemm_bias<<<g0, 256>>>(y0p, Wx_b1, b_b1, xzbp, BT, GG, 1024);

    float* est_h = out + (size_t)BT * 1024;
    float* est_c = est_h + BB * 1024;
    lstm_scan<<<NBLK, 256, SCAN_SMEM>>>(xzfp, xzbp, Wh_f1, Wh_b1, out, est_h, est_c);
}